// round 2
// baseline (speedup 1.0000x reference)
#include <cuda_runtime.h>
#include <math.h>

#define B      16
#define C      256
#define HW     4096
#define MEM    64
#define NTOK   4160
#define H3     1536
#define HID    512
#define NHEADS 8
#define DH     64

// -------- scratch (device globals, fully overwritten every launch) --------
__device__ float g_qkv[(size_t)B * H3 * NTOK];   // q rows 0..511, k 512..1023, v 1024..1535
__device__ float g_kmax[B * HID];
__device__ float g_ksum[B * HID];
__device__ float g_ctx[B * NHEADS * DH * DH];    // [b][h][d][e]
__device__ float g_att[(size_t)B * HID * HW];    // [b][c=h*64+e][t]

// =====================================================================
// K1: qkv = W_qkv @ x_ext   (M=1536, K=256, N=4160, batch=16)
// 128x128x16 tile, 256 threads, 8x8 micro-tile
// grid.x = 33: tiles 0..31 cover spatial tokens, tile 32 covers memory cols.
// For the memory tile we skip q rows (m0 < 512): q at tokens >= 4096 is unused.
// =====================================================================
__global__ __launch_bounds__(256) void gemm_qkv(
    const float* __restrict__ x, const float* __restrict__ mem,
    const float* __restrict__ W)
{
    __shared__ float As[16][128];   // As[k][m]
    __shared__ float Bs[16][128];   // Bs[k][n]
    int b  = blockIdx.z;
    int m0 = blockIdx.y * 128;
    int n0 = blockIdx.x * 128;
    int tid = threadIdx.x;
    int tx = tid & 15, ty = tid >> 4;

    const float* src;
    int stride, col0, ncols;
    if (n0 < HW) { src = x + (size_t)b * C * HW; stride = HW;  col0 = n0; ncols = 128; }
    else {
        if (m0 < HID) return;            // q not needed at memory tokens
        src = mem; stride = MEM; col0 = 0; ncols = MEM;
    }

    float acc[8][8];
    #pragma unroll
    for (int i = 0; i < 8; i++)
        #pragma unroll
        for (int j = 0; j < 8; j++) acc[i][j] = 0.f;

    for (int k0 = 0; k0 < C; k0 += 16) {
        __syncthreads();
        // A tile: 128 rows x 16 k, transposed store
        #pragma unroll
        for (int r = 0; r < 2; r++) {
            int f   = tid * 2 + r;        // 512 float4
            int row = f >> 2;
            int kc  = (f & 3) * 4;
            float4 v = *(const float4*)(W + (size_t)(m0 + row) * C + k0 + kc);
            As[kc + 0][row] = v.x;
            As[kc + 1][row] = v.y;
            As[kc + 2][row] = v.z;
            As[kc + 3][row] = v.w;
        }
        // B tile: 16 k x 128 n
        #pragma unroll
        for (int r = 0; r < 2; r++) {
            int f = tid * 2 + r;
            int k = f >> 5;
            int n = (f & 31) * 4;
            float4 v;
            if (n + 3 < ncols)
                v = *(const float4*)(src + (size_t)(k0 + k) * stride + col0 + n);
            else
                v = make_float4(0.f, 0.f, 0.f, 0.f);
            *(float4*)&Bs[k][n] = v;
        }
        __syncthreads();
        #pragma unroll
        for (int k = 0; k < 16; k++) {
            float a[8], bb[8];
            *(float4*)&a[0]  = *(float4*)&As[k][ty * 8];
            *(float4*)&a[4]  = *(float4*)&As[k][ty * 8 + 4];
            *(float4*)&bb[0] = *(float4*)&Bs[k][tx * 8];
            *(float4*)&bb[4] = *(float4*)&Bs[k][tx * 8 + 4];
            #pragma unroll
            for (int i = 0; i < 8; i++)
                #pragma unroll
                for (int j = 0; j < 8; j++)
                    acc[i][j] = fmaf(a[i], bb[j], acc[i][j]);
        }
    }
    float* outp = g_qkv + (size_t)b * H3 * NTOK;
    #pragma unroll
    for (int i = 0; i < 8; i++) {
        int m = m0 + ty * 8 + i;
        #pragma unroll
        for (int jc = 0; jc < 2; jc++) {
            int n = n0 + tx * 8 + jc * 4;
            if (n + 3 < NTOK) {
                float4 v = make_float4(acc[i][jc*4], acc[i][jc*4+1], acc[i][jc*4+2], acc[i][jc*4+3]);
                *(float4*)(outp + (size_t)m * NTOK + n) = v;
            }
        }
    }
}

// =====================================================================
// K2: per (b, k-channel) row softmax stats over N=4160 tokens
// =====================================================================
__global__ __launch_bounds__(256) void k_stats()
{
    int row = blockIdx.x;                 // 0..8191
    int b = row >> 9, c = row & 511;
    const float* p = g_qkv + ((size_t)b * H3 + HID + c) * NTOK;
    int tid = threadIdx.x;

    __shared__ float red1[8];
    __shared__ float red2[8];

    float m = -1e30f;
    for (int i = tid; i < NTOK; i += 256) m = fmaxf(m, p[i]);
    #pragma unroll
    for (int o = 16; o; o >>= 1) m = fmaxf(m, __shfl_xor_sync(0xffffffffu, m, o));
    if ((tid & 31) == 0) red1[tid >> 5] = m;
    __syncthreads();
    m = red1[0];
    #pragma unroll
    for (int w = 1; w < 8; w++) m = fmaxf(m, red1[w]);

    float s = 0.f;
    for (int i = tid; i < NTOK; i += 256) s += __expf(p[i] - m);
    #pragma unroll
    for (int o = 16; o; o >>= 1) s += __shfl_xor_sync(0xffffffffu, s, o);
    if ((tid & 31) == 0) red2[tid >> 5] = s;
    __syncthreads();
    if (tid == 0) {
        s = red2[0];
        for (int w = 1; w < 8; w++) s += red2[w];
        g_kmax[row] = m;
        g_ksum[row] = s;
    }
}

// =====================================================================
// K3: context[b][h][d][e] = sum_N softmax(k)[d,N] * v[e,N]
// one block per (b,h): 64x64 output, K=4160; 4x4 micro
// =====================================================================
__global__ __launch_bounds__(256) void k_context()
{
    int bh = blockIdx.x;                  // 0..127
    int b = bh >> 3, h = bh & 7;
    const float* kp = g_qkv + ((size_t)b * H3 + HID     + h * DH) * NTOK;
    const float* vp = g_qkv + ((size_t)b * H3 + 2 * HID + h * DH) * NTOK;

    __shared__ float Ks[64][68];          // [n][d]
    __shared__ float Vs[64][68];          // [n][e]
    __shared__ float skm[64], sinv[64];

    int tid = threadIdx.x;
    if (tid < 64) {
        skm[tid]  = g_kmax[bh * 64 + tid];
        sinv[tid] = 1.f / g_ksum[bh * 64 + tid];
    }
    int tx = tid & 15, ty = tid >> 4;
    float acc[4][4];
    #pragma unroll
    for (int i = 0; i < 4; i++)
        #pragma unroll
        for (int j = 0; j < 4; j++) acc[i][j] = 0.f;

    for (int n0 = 0; n0 < NTOK; n0 += 64) {
        __syncthreads();
        #pragma unroll
        for (int r = 0; r < 4; r++) {
            int f  = tid + r * 256;       // 1024 float4 per operand
            int d  = f >> 4;
            int n4 = (f & 15) * 4;
            float4 kv = *(const float4*)(kp + (size_t)d * NTOK + n0 + n4);
            float km = skm[d], ki = sinv[d];
            kv.x = __expf(kv.x - km) * ki;
            kv.y = __expf(kv.y - km) * ki;
            kv.z = __expf(kv.z - km) * ki;
            kv.w = __expf(kv.w - km) * ki;
            Ks[n4 + 0][d] = kv.x; Ks[n4 + 1][d] = kv.y;
            Ks[n4 + 2][d] = kv.z; Ks[n4 + 3][d] = kv.w;
            float4 vv = *(const float4*)(vp + (size_t)d * NTOK + n0 + n4);
            Vs[n4 + 0][d] = vv.x; Vs[n4 + 1][d] = vv.y;
            Vs[n4 + 2][d] = vv.z; Vs[n4 + 3][d] = vv.w;
        }
        __syncthreads();
        #pragma unroll
        for (int n = 0; n < 64; n++) {
            float4 a4 = *(float4*)&Ks[n][ty * 4];
            float4 b4 = *(float4*)&Vs[n][tx * 4];
            float a[4] = {a4.x, a4.y, a4.z, a4.w};
            float bb[4] = {b4.x, b4.y, b4.z, b4.w};
            #pragma unroll
            for (int i = 0; i < 4; i++)
                #pragma unroll
                for (int j = 0; j < 4; j++)
                    acc[i][j] = fmaf(a[i], bb[j], acc[i][j]);
        }
    }
    float* cp = g_ctx + (size_t)bh * DH * DH;
    #pragma unroll
    for (int i = 0; i < 4; i++)
        #pragma unroll
        for (int j = 0; j < 4; j++)
            cp[(ty * 4 + i) * DH + tx * 4 + j] = acc[i][j];
}

// =====================================================================
// K4: q softmax over d + out[e][t] = sum_d ctx[d][e] * q_sm[d][t] * SCALE
// block per (b, h, 64-token tile)
// =====================================================================
__global__ __launch_bounds__(256) void k_apply()
{
    int t0 = blockIdx.x * 64;
    int h  = blockIdx.y;
    int b  = blockIdx.z;
    const float* qp = g_qkv + ((size_t)b * H3 + h * DH) * NTOK;
    const float* cp = g_ctx + (size_t)(b * NHEADS + h) * DH * DH;

    __shared__ float Cs[64][68];   // [d][e]
    __shared__ float Qs[64][68];   // [d][t]
    __shared__ float red[256];
    __shared__ float smax[64], sinv[64];

    int tid = threadIdx.x;
    #pragma unroll
    for (int r = 0; r < 4; r++) {
        int f  = tid + r * 256;
        int d  = f >> 4;
        int c4 = (f & 15) * 4;
        *(float4*)&Cs[d][c4] = *(const float4*)(cp + d * DH + c4);
        *(float4*)&Qs[d][c4] = *(const float4*)(qp + (size_t)d * NTOK + t0 + c4);
    }
    __syncthreads();

    int t = tid & 63, part = tid >> 6;
    // pass 1: max over d
    float m = -1e30f;
    for (int d = part * 16; d < part * 16 + 16; d++) m = fmaxf(m, Qs[d][t]);
    red[tid] = m;
    __syncthreads();
    if (part == 0)
        smax[t] = fmaxf(fmaxf(red[t], red[64 + t]), fmaxf(red[128 + t], red[192 + t]));
    __syncthreads();
    m = smax[t];
    // pass 2: exp + sum
    float s = 0.f;
    for (int d = part * 16; d < part * 16 + 16; d++) {
        float e = __expf(Qs[d][t] - m);
        Qs[d][t] = e;
        s += e;
    }
    red[tid] = s;
    __syncthreads();
    if (part == 0)
        sinv[t] = 0.125f / (red[t] + red[64 + t] + red[128 + t] + red[192 + t]); // SCALE=1/8
    __syncthreads();
    float inv = sinv[t];
    for (int d = part * 16; d < part * 16 + 16; d++) Qs[d][t] *= inv;
    __syncthreads();

    // out[e][t] = sum_d Cs[d][e] * Qs[d][t]
    int tx = tid & 15, ty = tid >> 4;
    float acc[4][4];
    #pragma unroll
    for (int i = 0; i < 4; i++)
        #pragma unroll
        for (int j = 0; j < 4; j++) acc[i][j] = 0.f;
    #pragma unroll
    for (int d = 0; d < 64; d++) {
        float4 a4 = *(float4*)&Cs[d][ty * 4];
        float4 q4 = *(float4*)&Qs[d][tx * 4];
        float a[4]  = {a4.x, a4.y, a4.z, a4.w};
        float qq[4] = {q4.x, q4.y, q4.z, q4.w};
        #pragma unroll
        for (int i = 0; i < 4; i++)
            #pragma unroll
            for (int j = 0; j < 4; j++)
                acc[i][j] = fmaf(a[i], qq[j], acc[i][j]);
    }
    float* op = g_att + ((size_t)b * HID + h * DH) * HW;
    #pragma unroll
    for (int i = 0; i < 4; i++) {
        int e = ty * 4 + i;
        float4 v = make_float4(acc[i][0], acc[i][1], acc[i][2], acc[i][3]);
        *(float4*)(op + (size_t)e * HW + t0 + tx * 4) = v;
    }
}

// =====================================================================
// K5: y = W_out @ att + b_out   (M=256, K=512, N=4096, batch=16)
// =====================================================================
__global__ __launch_bounds__(256) void gemm_out(
    const float* __restrict__ W, const float* __restrict__ bias,
    float* __restrict__ y)
{
    __shared__ float As[16][128];
    __shared__ float Bs[16][128];
    int b  = blockIdx.z;
    int m0 = blockIdx.y * 128;
    int n0 = blockIdx.x * 128;
    int tid = threadIdx.x;
    int tx = tid & 15, ty = tid >> 4;
    const float* src = g_att + (size_t)b * HID * HW;

    float acc[8][8];
    #pragma unroll
    for (int i = 0; i < 8; i++)
        #pragma unroll
        for (int j = 0; j < 8; j++) acc[i][j] = 0.f;

    for (int k0 = 0; k0 < HID; k0 += 16) {
        __syncthreads();
        #pragma unroll
        for (int r = 0; r < 2; r++) {
            int f   = tid * 2 + r;
            int row = f >> 2;
            int kc  = (f & 3) * 4;
            float4 v = *(const float4*)(W + (size_t)(m0 + row) * HID + k0 + kc);
            As[kc + 0][row] = v.x;
            As[kc + 1][row] = v.y;
            As[kc + 2][row] = v.z;
            As[kc + 3][row] = v.w;
        }
        #pragma unroll
        for (int r = 0; r < 2; r++) {
            int f = tid * 2 + r;
            int k = f >> 5;
            int n = (f & 31) * 4;
            *(float4*)&Bs[k][n] = *(const float4*)(src + (size_t)(k0 + k) * HW + n0 + n);
        }
        __syncthreads();
        #pragma unroll
        for (int k = 0; k < 16; k++) {
            float a[8], bb[8];
            *(float4*)&a[0]  = *(float4*)&As[k][ty * 8];
            *(float4*)&a[4]  = *(float4*)&As[k][ty * 8 + 4];
            *(float4*)&bb[0] = *(float4*)&Bs[k][tx * 8];
            *(float4*)&bb[4] = *(float4*)&Bs[k][tx * 8 + 4];
            #pragma unroll
            for (int i = 0; i < 8; i++)
                #pragma unroll
                for (int j = 0; j < 8; j++)
                    acc[i][j] = fmaf(a[i], bb[j], acc[i][j]);
        }
    }
    float* outp = y + (size_t)b * C * HW;
    #pragma unroll
    for (int i = 0; i < 8; i++) {
        int m = m0 + ty * 8 + i;
        float bi = bias[m];
        #pragma unroll
        for (int jc = 0; jc < 2; jc++) {
            int n = n0 + tx * 8 + jc * 4;
            float4 v = make_float4(acc[i][jc*4] + bi, acc[i][jc*4+1] + bi,
                                   acc[i][jc*4+2] + bi, acc[i][jc*4+3] + bi);
            *(float4*)(outp + (size_t)m * HW + n) = v;
        }
    }
}

// =====================================================================
// K6: channel LayerNorm over C=256 per token, in place on d_out
// =====================================================================
__global__ __launch_bounds__(256) void k_ln(
    float* __restrict__ y, const float* __restrict__ g, const float* __restrict__ beta)
{
    __shared__ float tile[256][33];
    __shared__ float sg[256], sb[256];
    int b  = blockIdx.y;
    int t0 = blockIdx.x * 32;
    int tid = threadIdx.x;
    sg[tid] = g[tid];
    sb[tid] = beta[tid];
    float* base = y + (size_t)b * C * HW;
    #pragma unroll 8
    for (int r = 0; r < 32; r++) {
        int idx = tid + r * 256;
        int c = idx >> 5, t = idx & 31;
        tile[c][t] = base[(size_t)c * HW + t0 + t];
    }
    __syncthreads();
    int w = tid >> 5, lane = tid & 31;
    #pragma unroll
    for (int tt = 0; tt < 4; tt++) {
        int t = w * 4 + tt;
        float s = 0.f, sq = 0.f;
        #pragma unroll
        for (int k = 0; k < 8; k++) {
            float v = tile[lane + 32 * k][t];
            s += v;
            sq += v * v;
        }
        #pragma unroll
        for (int o = 16; o; o >>= 1) {
            s  += __shfl_xor_sync(0xffffffffu, s, o);
            sq += __shfl_xor_sync(0xffffffffu, sq, o);
        }
        float mean = s * (1.f / 256.f);
        float var  = sq * (1.f / 256.f) - mean * mean;
        float rstd = rsqrtf(var + 1e-5f);
        #pragma unroll
        for (int k = 0; k < 8; k++) {
            int c = lane + 32 * k;
            tile[c][t] = (tile[c][t] - mean) * rstd * sg[c] + sb[c];
        }
    }
    __syncthreads();
    #pragma unroll 8
    for (int r = 0; r < 32; r++) {
        int idx = tid + r * 256;
        int c = idx >> 5, t = idx & 31;
        base[(size_t)c * HW + t0 + t] = tile[c][t];
    }
}

// =====================================================================
extern "C" void kernel_launch(void* const* d_in, const int* in_sizes, int n_in,
                              void* d_out, int out_size)
{
    const float* x    = (const float*)d_in[0];
    const float* mem  = (const float*)d_in[1];
    const float* Wqkv = (const float*)d_in[2];
    const float* Wout = (const float*)d_in[3];
    const float* bout = (const float*)d_in[4];
    const float* lng  = (const float*)d_in[5];
    const float* lnb  = (const float*)d_in[6];
    float* y = (float*)d_out;

    gemm_qkv<<<dim3(33, 12, B), 256>>>(x, mem, Wqkv);      // N tiles: 33 (last = memory cols)
    k_stats<<<B * HID, 256>>>();
    k_context<<<B * NHEADS, 256>>>();
    k_apply<<<dim3(HW / 64, NHEADS, B), 256>>>();
    gemm_out<<<dim3(HW / 128, C / 128, B), 256>>>(Wout, bout, y);
    k_ln<<<dim3(HW / 32, B), 256>>>(y, lng, lnb);
}

// round 3
// speedup vs baseline: 2.2603x; 2.2603x over previous
#include <cuda_runtime.h>
#include <math.h>
#include <stdint.h>

#define B      16
#define C      256
#define HW     4096
#define MEM    64
#define NTOK   4160
#define H3     1536
#define HID    512
#define NHEADS 8
#define DH     64

// -------- scratch (device globals, fully overwritten every launch) --------
__device__ float g_qkv[(size_t)B * H3 * NTOK];   // q rows 0..511, k 512..1023, v 1024..1535
__device__ float g_kmax[B * HID];
__device__ float g_ksum[B * HID];
__device__ float g_ctx[B * NHEADS * DH * DH];    // [b][h][d][e]
__device__ float g_att[(size_t)B * HID * HW];    // [b][c=h*64+e][t]

// ---------------- tf32 mma helpers ----------------
__device__ __forceinline__ uint32_t f2tf32(float f) {
    uint32_t r;
    asm("cvt.rna.tf32.f32 %0, %1;" : "=r"(r) : "f"(f));
    return r;
}

__device__ __forceinline__ void mma_tf32(float* d, const uint32_t* a, const uint32_t* b) {
    asm volatile(
        "mma.sync.aligned.m16n8k8.row.col.f32.tf32.tf32.f32 "
        "{%0,%1,%2,%3}, {%4,%5,%6,%7}, {%8,%9}, {%0,%1,%2,%3};\n"
        : "+f"(d[0]), "+f"(d[1]), "+f"(d[2]), "+f"(d[3])
        : "r"(a[0]), "r"(a[1]), "r"(a[2]), "r"(a[3]), "r"(b[0]), "r"(b[1]));
}

// =====================================================================
// K1: qkv = W_qkv @ x_ext   (M=1536, K=256, N=4160, batch=16)  tf32 MMA
// 128x128 block tile, k-tile 32, 8 warps (2m x 4n), 64x32 per warp.
// grid.x = 33: tiles 0..31 spatial tokens, tile 32 memory cols (64 valid).
// =====================================================================
__global__ __launch_bounds__(256) void gemm_qkv(
    const float* __restrict__ x, const float* __restrict__ mem,
    const float* __restrict__ W)
{
    __shared__ uint32_t As[128][36];    // A[m][k], stride 36 (bank = 4m+k)
    __shared__ uint32_t Bs[32][136];    // B[k][n], stride 136 (bank = 8k+n)

    int b  = blockIdx.z;
    int m0 = blockIdx.y * 128;
    int n0 = blockIdx.x * 128;
    int tid  = threadIdx.x;
    int lane = tid & 31, wid = tid >> 5;
    int warp_m = (wid & 1) * 64;
    int warp_n = (wid >> 1) * 32;
    int g = lane >> 2, tg = lane & 3;

    const float* src;
    int stride, col0, ncols;
    if (n0 < HW) { src = x + (size_t)b * C * HW; stride = HW;  col0 = n0; ncols = 128; }
    else {
        if (m0 < HID) return;            // q not needed at memory tokens
        src = mem; stride = MEM; col0 = 0; ncols = MEM;
    }

    float acc[4][4][4];
    #pragma unroll
    for (int mf = 0; mf < 4; mf++)
        #pragma unroll
        for (int nf = 0; nf < 4; nf++)
            #pragma unroll
            for (int i = 0; i < 4; i++) acc[mf][nf][i] = 0.f;

    for (int k0 = 0; k0 < C; k0 += 32) {
        __syncthreads();
        // A tile: 128 m x 32 k
        #pragma unroll
        for (int r = 0; r < 4; r++) {
            int idx = tid + r * 256;           // 0..1023 float4 slots
            int row = idx >> 3;
            int kc  = (idx & 7) * 4;
            float4 v = *(const float4*)(W + (size_t)(m0 + row) * C + k0 + kc);
            As[row][kc + 0] = f2tf32(v.x);
            As[row][kc + 1] = f2tf32(v.y);
            As[row][kc + 2] = f2tf32(v.z);
            As[row][kc + 3] = f2tf32(v.w);
        }
        // B tile: 32 k x 128 n
        #pragma unroll
        for (int r = 0; r < 4; r++) {
            int idx = tid + r * 256;
            int row = idx >> 5;
            int nc  = (idx & 31) * 4;
            float4 v;
            if (nc + 3 < ncols)
                v = *(const float4*)(src + (size_t)(k0 + row) * stride + col0 + nc);
            else
                v = make_float4(0.f, 0.f, 0.f, 0.f);
            Bs[row][nc + 0] = f2tf32(v.x);
            Bs[row][nc + 1] = f2tf32(v.y);
            Bs[row][nc + 2] = f2tf32(v.z);
            Bs[row][nc + 3] = f2tf32(v.w);
        }
        __syncthreads();
        #pragma unroll
        for (int ks = 0; ks < 4; ks++) {       // k-step of 8
            uint32_t a[4][4], bb[4][2];
            #pragma unroll
            for (int mf = 0; mf < 4; mf++) {
                int row = warp_m + mf * 16 + g;
                a[mf][0] = As[row    ][ks * 8 + tg];
                a[mf][1] = As[row + 8][ks * 8 + tg];
                a[mf][2] = As[row    ][ks * 8 + tg + 4];
                a[mf][3] = As[row + 8][ks * 8 + tg + 4];
            }
            #pragma unroll
            for (int nf = 0; nf < 4; nf++) {
                bb[nf][0] = Bs[ks * 8 + tg    ][warp_n + nf * 8 + g];
                bb[nf][1] = Bs[ks * 8 + tg + 4][warp_n + nf * 8 + g];
            }
            #pragma unroll
            for (int mf = 0; mf < 4; mf++)
                #pragma unroll
                for (int nf = 0; nf < 4; nf++)
                    mma_tf32(acc[mf][nf], a[mf], bb[nf]);
        }
    }

    float* outp = g_qkv + (size_t)b * H3 * NTOK;
    #pragma unroll
    for (int mf = 0; mf < 4; mf++) {
        #pragma unroll
        for (int nf = 0; nf < 4; nf++) {
            int n = n0 + warp_n + nf * 8 + tg * 2;
            if (n < NTOK) {
                int m = m0 + warp_m + mf * 16 + g;
                *(float2*)(outp + (size_t)m * NTOK + n) =
                    make_float2(acc[mf][nf][0], acc[mf][nf][1]);
                *(float2*)(outp + (size_t)(m + 8) * NTOK + n) =
                    make_float2(acc[mf][nf][2], acc[mf][nf][3]);
            }
        }
    }
}

// =====================================================================
// K2: per (b, k-channel) row softmax stats over N=4160 tokens
// =====================================================================
__global__ __launch_bounds__(256) void k_stats()
{
    int row = blockIdx.x;                 // 0..8191
    int b = row >> 9, c = row & 511;
    const float* p = g_qkv + ((size_t)b * H3 + HID + c) * NTOK;
    int tid = threadIdx.x;

    __shared__ float red1[8];
    __shared__ float red2[8];

    float m = -1e30f;
    for (int i = tid; i < NTOK; i += 256) m = fmaxf(m, p[i]);
    #pragma unroll
    for (int o = 16; o; o >>= 1) m = fmaxf(m, __shfl_xor_sync(0xffffffffu, m, o));
    if ((tid & 31) == 0) red1[tid >> 5] = m;
    __syncthreads();
    m = red1[0];
    #pragma unroll
    for (int w = 1; w < 8; w++) m = fmaxf(m, red1[w]);

    float s = 0.f;
    for (int i = tid; i < NTOK; i += 256) s += __expf(p[i] - m);
    #pragma unroll
    for (int o = 16; o; o >>= 1) s += __shfl_xor_sync(0xffffffffu, s, o);
    if ((tid & 31) == 0) red2[tid >> 5] = s;
    __syncthreads();
    if (tid == 0) {
        s = red2[0];
        for (int w = 1; w < 8; w++) s += red2[w];
        g_kmax[row] = m;
        g_ksum[row] = s;
    }
}

// =====================================================================
// K3: context[b][h][d][e] = sum_N softmax(k)[d,N] * v[e,N]
// =====================================================================
__global__ __launch_bounds__(256) void k_context()
{
    int bh = blockIdx.x;                  // 0..127
    int b = bh >> 3, h = bh & 7;
    const float* kp = g_qkv + ((size_t)b * H3 + HID     + h * DH) * NTOK;
    const float* vp = g_qkv + ((size_t)b * H3 + 2 * HID + h * DH) * NTOK;

    __shared__ float Ks[64][68];          // [n][d]
    __shared__ float Vs[64][68];          // [n][e]
    __shared__ float skm[64], sinv[64];

    int tid = threadIdx.x;
    if (tid < 64) {
        skm[tid]  = g_kmax[bh * 64 + tid];
        sinv[tid] = 1.f / g_ksum[bh * 64 + tid];
    }
    int tx = tid & 15, ty = tid >> 4;
    float acc[4][4];
    #pragma unroll
    for (int i = 0; i < 4; i++)
        #pragma unroll
        for (int j = 0; j < 4; j++) acc[i][j] = 0.f;

    for (int n0 = 0; n0 < NTOK; n0 += 64) {
        __syncthreads();
        #pragma unroll
        for (int r = 0; r < 4; r++) {
            int f  = tid + r * 256;       // 1024 float4 per operand
            int d  = f >> 4;
            int n4 = (f & 15) * 4;
            float4 kv = *(const float4*)(kp + (size_t)d * NTOK + n0 + n4);
            float km = skm[d], ki = sinv[d];
            kv.x = __expf(kv.x - km) * ki;
            kv.y = __expf(kv.y - km) * ki;
            kv.z = __expf(kv.z - km) * ki;
            kv.w = __expf(kv.w - km) * ki;
            Ks[n4 + 0][d] = kv.x; Ks[n4 + 1][d] = kv.y;
            Ks[n4 + 2][d] = kv.z; Ks[n4 + 3][d] = kv.w;
            float4 vv = *(const float4*)(vp + (size_t)d * NTOK + n0 + n4);
            Vs[n4 + 0][d] = vv.x; Vs[n4 + 1][d] = vv.y;
            Vs[n4 + 2][d] = vv.z; Vs[n4 + 3][d] = vv.w;
        }
        __syncthreads();
        #pragma unroll
        for (int n = 0; n < 64; n++) {
            float4 a4 = *(float4*)&Ks[n][ty * 4];
            float4 b4 = *(float4*)&Vs[n][tx * 4];
            float a[4] = {a4.x, a4.y, a4.z, a4.w};
            float bb[4] = {b4.x, b4.y, b4.z, b4.w};
            #pragma unroll
            for (int i = 0; i < 4; i++)
                #pragma unroll
                for (int j = 0; j < 4; j++)
                    acc[i][j] = fmaf(a[i], bb[j], acc[i][j]);
        }
    }
    float* cp = g_ctx + (size_t)bh * DH * DH;
    #pragma unroll
    for (int i = 0; i < 4; i++)
        #pragma unroll
        for (int j = 0; j < 4; j++)
            cp[(ty * 4 + i) * DH + tx * 4 + j] = acc[i][j];
}

// =====================================================================
// K4: q softmax over d + out[e][t] = sum_d ctx[d][e] * q_sm[d][t] * SCALE
// =====================================================================
__global__ __launch_bounds__(256) void k_apply()
{
    int t0 = blockIdx.x * 64;
    int h  = blockIdx.y;
    int b  = blockIdx.z;
    const float* qp = g_qkv + ((size_t)b * H3 + h * DH) * NTOK;
    const float* cp = g_ctx + (size_t)(b * NHEADS + h) * DH * DH;

    __shared__ float Cs[64][68];   // [d][e]
    __shared__ float Qs[64][68];   // [d][t]
    __shared__ float red[256];
    __shared__ float smax[64], sinv[64];

    int tid = threadIdx.x;
    #pragma unroll
    for (int r = 0; r < 4; r++) {
        int f  = tid + r * 256;
        int d  = f >> 4;
        int c4 = (f & 15) * 4;
        *(float4*)&Cs[d][c4] = *(const float4*)(cp + d * DH + c4);
        *(float4*)&Qs[d][c4] = *(const float4*)(qp + (size_t)d * NTOK + t0 + c4);
    }
    __syncthreads();

    int t = tid & 63, part = tid >> 6;
    float m = -1e30f;
    for (int d = part * 16; d < part * 16 + 16; d++) m = fmaxf(m, Qs[d][t]);
    red[tid] = m;
    __syncthreads();
    if (part == 0)
        smax[t] = fmaxf(fmaxf(red[t], red[64 + t]), fmaxf(red[128 + t], red[192 + t]));
    __syncthreads();
    m = smax[t];
    float s = 0.f;
    for (int d = part * 16; d < part * 16 + 16; d++) {
        float e = __expf(Qs[d][t] - m);
        Qs[d][t] = e;
        s += e;
    }
    red[tid] = s;
    __syncthreads();
    if (part == 0)
        sinv[t] = 0.125f / (red[t] + red[64 + t] + red[128 + t] + red[192 + t]); // SCALE=1/8
    __syncthreads();
    float inv = sinv[t];
    for (int d = part * 16; d < part * 16 + 16; d++) Qs[d][t] *= inv;
    __syncthreads();

    int tx = tid & 15, ty = tid >> 4;
    float acc[4][4];
    #pragma unroll
    for (int i = 0; i < 4; i++)
        #pragma unroll
        for (int j = 0; j < 4; j++) acc[i][j] = 0.f;
    #pragma unroll
    for (int d = 0; d < 64; d++) {
        float4 a4 = *(float4*)&Cs[d][ty * 4];
        float4 q4 = *(float4*)&Qs[d][tx * 4];
        float a[4]  = {a4.x, a4.y, a4.z, a4.w};
        float qq[4] = {q4.x, q4.y, q4.z, q4.w};
        #pragma unroll
        for (int i = 0; i < 4; i++)
            #pragma unroll
            for (int j = 0; j < 4; j++)
                acc[i][j] = fmaf(a[i], qq[j], acc[i][j]);
    }
    float* op = g_att + ((size_t)b * HID + h * DH) * HW;
    #pragma unroll
    for (int i = 0; i < 4; i++) {
        int e = ty * 4 + i;
        float4 v = make_float4(acc[i][0], acc[i][1], acc[i][2], acc[i][3]);
        *(float4*)(op + (size_t)e * HW + t0 + tx * 4) = v;
    }
}

// =====================================================================
// K5: y = W_out @ att + b_out   (M=256, K=512, N=4096, batch=16)  tf32 MMA
// =====================================================================
__global__ __launch_bounds__(256) void gemm_out(
    const float* __restrict__ W, const float* __restrict__ bias,
    float* __restrict__ y)
{
    __shared__ uint32_t As[128][36];
    __shared__ uint32_t Bs[32][136];

    int b  = blockIdx.z;
    int m0 = blockIdx.y * 128;
    int n0 = blockIdx.x * 128;
    int tid  = threadIdx.x;
    int lane = tid & 31, wid = tid >> 5;
    int warp_m = (wid & 1) * 64;
    int warp_n = (wid >> 1) * 32;
    int g = lane >> 2, tg = lane & 3;
    const float* src = g_att + (size_t)b * HID * HW;

    float acc[4][4][4];
    #pragma unroll
    for (int mf = 0; mf < 4; mf++)
        #pragma unroll
        for (int nf = 0; nf < 4; nf++)
            #pragma unroll
            for (int i = 0; i < 4; i++) acc[mf][nf][i] = 0.f;

    for (int k0 = 0; k0 < HID; k0 += 32) {
        __syncthreads();
        #pragma unroll
        for (int r = 0; r < 4; r++) {
            int idx = tid + r * 256;
            int row = idx >> 3;
            int kc  = (idx & 7) * 4;
            float4 v = *(const float4*)(W + (size_t)(m0 + row) * HID + k0 + kc);
            As[row][kc + 0] = f2tf32(v.x);
            As[row][kc + 1] = f2tf32(v.y);
            As[row][kc + 2] = f2tf32(v.z);
            As[row][kc + 3] = f2tf32(v.w);
        }
        #pragma unroll
        for (int r = 0; r < 4; r++) {
            int idx = tid + r * 256;
            int row = idx >> 5;
            int nc  = (idx & 31) * 4;
            float4 v = *(const float4*)(src + (size_t)(k0 + row) * HW + n0 + nc);
            Bs[row][nc + 0] = f2tf32(v.x);
            Bs[row][nc + 1] = f2tf32(v.y);
            Bs[row][nc + 2] = f2tf32(v.z);
            Bs[row][nc + 3] = f2tf32(v.w);
        }
        __syncthreads();
        #pragma unroll
        for (int ks = 0; ks < 4; ks++) {
            uint32_t a[4][4], bb[4][2];
            #pragma unroll
            for (int mf = 0; mf < 4; mf++) {
                int row = warp_m + mf * 16 + g;
                a[mf][0] = As[row    ][ks * 8 + tg];
                a[mf][1] = As[row + 8][ks * 8 + tg];
                a[mf][2] = As[row    ][ks * 8 + tg + 4];
                a[mf][3] = As[row + 8][ks * 8 + tg + 4];
            }
            #pragma unroll
            for (int nf = 0; nf < 4; nf++) {
                bb[nf][0] = Bs[ks * 8 + tg    ][warp_n + nf * 8 + g];
                bb[nf][1] = Bs[ks * 8 + tg + 4][warp_n + nf * 8 + g];
            }
            #pragma unroll
            for (int mf = 0; mf < 4; mf++)
                #pragma unroll
                for (int nf = 0; nf < 4; nf++)
                    mma_tf32(acc[mf][nf], a[mf], bb[nf]);
        }
    }

    float* outp = y + (size_t)b * C * HW;
    #pragma unroll
    for (int mf = 0; mf < 4; mf++) {
        int m = m0 + warp_m + mf * 16 + g;
        float bi0 = bias[m], bi1 = bias[m + 8];
        #pragma unroll
        for (int nf = 0; nf < 4; nf++) {
            int n = n0 + warp_n + nf * 8 + tg * 2;
            *(float2*)(outp + (size_t)m * HW + n) =
                make_float2(acc[mf][nf][0] + bi0, acc[mf][nf][1] + bi0);
            *(float2*)(outp + (size_t)(m + 8) * HW + n) =
                make_float2(acc[mf][nf][2] + bi1, acc[mf][nf][3] + bi1);
        }
    }
}

// =====================================================================
// K6: channel LayerNorm over C=256 per token, in place on d_out
// =====================================================================
__global__ __launch_bounds__(256) void k_ln(
    float* __restrict__ y, const float* __restrict__ g, const float* __restrict__ beta)
{
    __shared__ float tile[256][33];
    __shared__ float sg[256], sb[256];
    int b  = blockIdx.y;
    int t0 = blockIdx.x * 32;
    int tid = threadIdx.x;
    sg[tid] = g[tid];
    sb[tid] = beta[tid];
    float* base = y + (size_t)b * C * HW;
    #pragma unroll 8
    for (int r = 0; r < 32; r++) {
        int idx = tid + r * 256;
        int c = idx >> 5, t = idx & 31;
        tile[c][t] = base[(size_t)c * HW + t0 + t];
    }
    __syncthreads();
    int w = tid >> 5, lane = tid & 31;
    #pragma unroll
    for (int tt = 0; tt < 4; tt++) {
        int t = w * 4 + tt;
        float s = 0.f, sq = 0.f;
        #pragma unroll
        for (int k = 0; k < 8; k++) {
            float v = tile[lane + 32 * k][t];
            s += v;
            sq += v * v;
        }
        #pragma unroll
        for (int o = 16; o; o >>= 1) {
            s  += __shfl_xor_sync(0xffffffffu, s, o);
            sq += __shfl_xor_sync(0xffffffffu, sq, o);
        }
        float mean = s * (1.f / 256.f);
        float var  = sq * (1.f / 256.f) - mean * mean;
        float rstd = rsqrtf(var + 1e-5f);
        #pragma unroll
        for (int k = 0; k < 8; k++) {
            int c = lane + 32 * k;
            tile[c][t] = (tile[c][t] - mean) * rstd * sg[c] + sb[c];
        }
    }
    __syncthreads();
    #pragma unroll 8
    for (int r = 0; r < 32; r++) {
        int idx = tid + r * 256;
        int c = idx >> 5, t = idx & 31;
        base[(size_t)c * HW + t0 + t] = tile[c][t];
    }
}

// =====================================================================
extern "C" void kernel_launch(void* const* d_in, const int* in_sizes, int n_in,
                              void* d_out, int out_size)
{
    const float* x    = (const float*)d_in[0];
    const float* mem  = (const float*)d_in[1];
    const float* Wqkv = (const float*)d_in[2];
    const float* Wout = (const float*)d_in[3];
    const float* bout = (const float*)d_in[4];
    const float* lng  = (const float*)d_in[5];
    const float* lnb  = (const float*)d_in[6];
    float* y = (float*)d_out;

    gemm_qkv<<<dim3(33, 12, B), 256>>>(x, mem, Wqkv);      // N tiles: 33 (last = memory cols)
    k_stats<<<B * HID, 256>>>();
    k_context<<<B * NHEADS, 256>>>();
    k_apply<<<dim3(HW / 64, NHEADS, B), 256>>>();
    gemm_out<<<dim3(HW / 128, C / 128, B), 256>>>(Wout, bout, y);
    k_ln<<<dim3(HW / 32, B), 256>>>(y, lng, lnb);
}

// round 4
// speedup vs baseline: 2.8981x; 1.2822x over previous
#include <cuda_runtime.h>
#include <math.h>
#include <stdint.h>

#define B      16
#define C      256
#define HW     4096
#define MEM    64
#define NTOK   4160
#define H3     1536
#define HID    512
#define NHEADS 8
#define DH     64
#define NCHUNK 13
#define CHTOK  320     // NTOK / NCHUNK

// -------- scratch (device globals, fully overwritten every launch) --------
__device__ float g_qkv[(size_t)B * H3 * NTOK];     // q rows 0..511, k 512..1023, v 1024..1535
__device__ float g_kmax[B * HID];
__device__ float g_ksum[B * HID];
__device__ float g_qexp[(size_t)B * HID * HW];     // softmaxed+scaled q, [b][h*64+d][t]
__device__ float g_ctxp[(size_t)NCHUNK * B * NHEADS * DH * DH];  // partial ctxT [ch][bh][e][d]
__device__ float g_ctxT[B * NHEADS * DH * DH];     // ctxT [bh][e][d]
__device__ float g_wc[(size_t)B * C * HID];        // folded weights [b][o][h*64+d]

// ---------------- tf32 mma helpers ----------------
__device__ __forceinline__ uint32_t f2tf32(float f) {
    uint32_t r;
    asm("cvt.rna.tf32.f32 %0, %1;" : "=r"(r) : "f"(f));
    return r;
}

__device__ __forceinline__ void mma_tf32(float* d, const uint32_t* a, const uint32_t* b) {
    asm volatile(
        "mma.sync.aligned.m16n8k8.row.col.f32.tf32.tf32.f32 "
        "{%0,%1,%2,%3}, {%4,%5,%6,%7}, {%8,%9}, {%0,%1,%2,%3};\n"
        : "+f"(d[0]), "+f"(d[1]), "+f"(d[2]), "+f"(d[3])
        : "r"(a[0]), "r"(a[1]), "r"(a[2]), "r"(a[3]), "r"(b[0]), "r"(b[1]));
}

// =====================================================================
// K1: qkv = W_qkv @ x_ext   (M=1536, K=256, N=4160, batch=16)  tf32 MMA
// =====================================================================
__global__ __launch_bounds__(256) void gemm_qkv(
    const float* __restrict__ x, const float* __restrict__ mem,
    const float* __restrict__ W)
{
    __shared__ uint32_t As[128][36];
    __shared__ uint32_t Bs[32][136];

    int b  = blockIdx.z;
    int m0 = blockIdx.y * 128;
    int n0 = blockIdx.x * 128;
    int tid  = threadIdx.x;
    int lane = tid & 31, wid = tid >> 5;
    int warp_m = (wid & 1) * 64;
    int warp_n = (wid >> 1) * 32;
    int g = lane >> 2, tg = lane & 3;

    const float* src;
    int stride, col0, ncols;
    if (n0 < HW) { src = x + (size_t)b * C * HW; stride = HW;  col0 = n0; ncols = 128; }
    else {
        if (m0 < HID) return;            // q not needed at memory tokens
        src = mem; stride = MEM; col0 = 0; ncols = MEM;
    }

    float acc[4][4][4];
    #pragma unroll
    for (int mf = 0; mf < 4; mf++)
        #pragma unroll
        for (int nf = 0; nf < 4; nf++)
            #pragma unroll
            for (int i = 0; i < 4; i++) acc[mf][nf][i] = 0.f;

    for (int k0 = 0; k0 < C; k0 += 32) {
        __syncthreads();
        #pragma unroll
        for (int r = 0; r < 4; r++) {
            int idx = tid + r * 256;
            int row = idx >> 3;
            int kc  = (idx & 7) * 4;
            float4 v = *(const float4*)(W + (size_t)(m0 + row) * C + k0 + kc);
            As[row][kc + 0] = f2tf32(v.x);
            As[row][kc + 1] = f2tf32(v.y);
            As[row][kc + 2] = f2tf32(v.z);
            As[row][kc + 3] = f2tf32(v.w);
        }
        #pragma unroll
        for (int r = 0; r < 4; r++) {
            int idx = tid + r * 256;
            int row = idx >> 5;
            int nc  = (idx & 31) * 4;
            float4 v;
            if (nc + 3 < ncols)
                v = *(const float4*)(src + (size_t)(k0 + row) * stride + col0 + nc);
            else
                v = make_float4(0.f, 0.f, 0.f, 0.f);
            Bs[row][nc + 0] = f2tf32(v.x);
            Bs[row][nc + 1] = f2tf32(v.y);
            Bs[row][nc + 2] = f2tf32(v.z);
            Bs[row][nc + 3] = f2tf32(v.w);
        }
        __syncthreads();
        #pragma unroll
        for (int ks = 0; ks < 4; ks++) {
            uint32_t a[4][4], bb[4][2];
            #pragma unroll
            for (int mf = 0; mf < 4; mf++) {
                int row = warp_m + mf * 16 + g;
                a[mf][0] = As[row    ][ks * 8 + tg];
                a[mf][1] = As[row + 8][ks * 8 + tg];
                a[mf][2] = As[row    ][ks * 8 + tg + 4];
                a[mf][3] = As[row + 8][ks * 8 + tg + 4];
            }
            #pragma unroll
            for (int nf = 0; nf < 4; nf++) {
                bb[nf][0] = Bs[ks * 8 + tg    ][warp_n + nf * 8 + g];
                bb[nf][1] = Bs[ks * 8 + tg + 4][warp_n + nf * 8 + g];
            }
            #pragma unroll
            for (int mf = 0; mf < 4; mf++)
                #pragma unroll
                for (int nf = 0; nf < 4; nf++)
                    mma_tf32(acc[mf][nf], a[mf], bb[nf]);
        }
    }

    float* outp = g_qkv + (size_t)b * H3 * NTOK;
    #pragma unroll
    for (int mf = 0; mf < 4; mf++) {
        #pragma unroll
        for (int nf = 0; nf < 4; nf++) {
            int n = n0 + warp_n + nf * 8 + tg * 2;
            if (n < NTOK) {
                int m = m0 + warp_m + mf * 16 + g;
                *(float2*)(outp + (size_t)m * NTOK + n) =
                    make_float2(acc[mf][nf][0], acc[mf][nf][1]);
                *(float2*)(outp + (size_t)(m + 8) * NTOK + n) =
                    make_float2(acc[mf][nf][2], acc[mf][nf][3]);
            }
        }
    }
}

// =====================================================================
// K2: per (b, k-channel) softmax stats over N=4160 tokens
// =====================================================================
__global__ __launch_bounds__(256) void k_stats()
{
    int row = blockIdx.x;                 // 0..8191
    int b = row >> 9, c = row & 511;
    const float* p = g_qkv + ((size_t)b * H3 + HID + c) * NTOK;
    int tid = threadIdx.x;

    __shared__ float red1[8];
    __shared__ float red2[8];

    float m = -1e30f;
    for (int i = tid; i < NTOK; i += 256) m = fmaxf(m, p[i]);
    #pragma unroll
    for (int o = 16; o; o >>= 1) m = fmaxf(m, __shfl_xor_sync(0xffffffffu, m, o));
    if ((tid & 31) == 0) red1[tid >> 5] = m;
    __syncthreads();
    m = red1[0];
    #pragma unroll
    for (int w = 1; w < 8; w++) m = fmaxf(m, red1[w]);

    float s = 0.f;
    for (int i = tid; i < NTOK; i += 256) s += __expf(p[i] - m);
    #pragma unroll
    for (int o = 16; o; o >>= 1) s += __shfl_xor_sync(0xffffffffu, s, o);
    if ((tid & 31) == 0) red2[tid >> 5] = s;
    __syncthreads();
    if (tid == 0) {
        s = red2[0];
        for (int w = 1; w < 8; w++) s += red2[w];
        g_kmax[row] = m;
        g_ksum[row] = s;
    }
}

// =====================================================================
// K3: q softmax over d (per b,h,token), writes qexp = exp(q-max)*SCALE/sum
// block = (b, h, 128-token tile); smem tile 64 x 128
// =====================================================================
__global__ __launch_bounds__(256) void q_softmax()
{
    __shared__ float Q[64][132];
    __shared__ float sred[2][128];
    __shared__ float sinv[128];

    int t0 = blockIdx.x * 128;
    int h  = blockIdx.y;
    int b  = blockIdx.z;
    int tid = threadIdx.x;
    const float* qp = g_qkv + ((size_t)b * H3 + h * DH) * NTOK;

    #pragma unroll
    for (int r = 0; r < 8; r++) {
        int f = tid + r * 256;
        int row = f >> 5, c4 = (f & 31) * 4;
        *(float4*)&Q[row][c4] = *(const float4*)(qp + (size_t)row * NTOK + t0 + c4);
    }
    __syncthreads();

    int t = tid & 127, half = tid >> 7;
    float m = -1e30f;
    for (int d = half * 32; d < half * 32 + 32; d++) m = fmaxf(m, Q[d][t]);
    sred[half][t] = m;
    __syncthreads();
    m = fmaxf(sred[0][t], sred[1][t]);
    float s = 0.f;
    for (int d = half * 32; d < half * 32 + 32; d++) {
        float e = __expf(Q[d][t] - m);
        Q[d][t] = e;
        s += e;
    }
    __syncthreads();   // sred reuse
    sred[half][t] = s;
    __syncthreads();
    if (half == 0) sinv[t] = 0.125f / (sred[0][t] + sred[1][t]);   // SCALE folded
    __syncthreads();

    float* op = g_qexp + ((size_t)b * HID + h * DH) * HW;
    #pragma unroll
    for (int r = 0; r < 8; r++) {
        int f = tid + r * 256;
        int row = f >> 5, c4 = (f & 31) * 4;
        float4 iv = *(float4*)&sinv[c4];
        float4 v;
        v.x = Q[row][c4 + 0] * iv.x;
        v.y = Q[row][c4 + 1] * iv.y;
        v.z = Q[row][c4 + 2] * iv.z;
        v.w = Q[row][c4 + 3] * iv.w;
        *(float4*)(op + (size_t)row * HW + t0 + c4) = v;
    }
}

// =====================================================================
// K4: partial ctxT[e][d] = sum_n v[e,n] * ksm[d,n] over a 320-token chunk
// tf32 mma, grid (13 chunks, 8 heads, 16 batch)
// =====================================================================
__global__ __launch_bounds__(256) void k_context_p()
{
    __shared__ uint32_t Ks[64][68];       // ksm[d][nt]  (B operand, n=d)
    __shared__ uint32_t Vs[64][68];       // v[e][nt]    (A operand, m=e)
    __shared__ float skm[64], sinv[64];

    int ch = blockIdx.x;
    int h  = blockIdx.y;
    int b  = blockIdx.z;
    int bh = b * NHEADS + h;
    const float* kp = g_qkv + ((size_t)b * H3 + HID     + h * DH) * NTOK;
    const float* vp = g_qkv + ((size_t)b * H3 + 2 * HID + h * DH) * NTOK;

    int tid = threadIdx.x;
    int lane = tid & 31, wid = tid >> 5;
    int g = lane >> 2, tg = lane & 3;
    int we = (wid & 1) * 32;              // e range per warp: 32
    int wd = (wid >> 1) * 16;             // d range per warp: 16

    if (tid < 64) {
        skm[tid]  = g_kmax[bh * 64 + tid];
        sinv[tid] = 1.f / g_ksum[bh * 64 + tid];
    }

    float acc[2][2][4];
    #pragma unroll
    for (int mf = 0; mf < 2; mf++)
        #pragma unroll
        for (int nf = 0; nf < 2; nf++)
            #pragma unroll
            for (int i = 0; i < 4; i++) acc[mf][nf][i] = 0.f;

    for (int tile = 0; tile < CHTOK / 64; tile++) {
        int n0 = ch * CHTOK + tile * 64;
        __syncthreads();
        #pragma unroll
        for (int r = 0; r < 4; r++) {
            int f = tid + r * 256;
            int row = f >> 4, c4 = (f & 15) * 4;
            float4 kv = *(const float4*)(kp + (size_t)row * NTOK + n0 + c4);
            float km = skm[row], ki = sinv[row];
            Ks[row][c4 + 0] = f2tf32(__expf(kv.x - km) * ki);
            Ks[row][c4 + 1] = f2tf32(__expf(kv.y - km) * ki);
            Ks[row][c4 + 2] = f2tf32(__expf(kv.z - km) * ki);
            Ks[row][c4 + 3] = f2tf32(__expf(kv.w - km) * ki);
            float4 vv = *(const float4*)(vp + (size_t)row * NTOK + n0 + c4);
            Vs[row][c4 + 0] = f2tf32(vv.x);
            Vs[row][c4 + 1] = f2tf32(vv.y);
            Vs[row][c4 + 2] = f2tf32(vv.z);
            Vs[row][c4 + 3] = f2tf32(vv.w);
        }
        __syncthreads();
        #pragma unroll
        for (int ks = 0; ks < 8; ks++) {
            uint32_t a[2][4], bb[2][2];
            #pragma unroll
            for (int mf = 0; mf < 2; mf++) {
                int row = we + mf * 16 + g;
                a[mf][0] = Vs[row    ][ks * 8 + tg];
                a[mf][1] = Vs[row + 8][ks * 8 + tg];
                a[mf][2] = Vs[row    ][ks * 8 + tg + 4];
                a[mf][3] = Vs[row + 8][ks * 8 + tg + 4];
            }
            #pragma unroll
            for (int nf = 0; nf < 2; nf++) {
                bb[nf][0] = Ks[wd + nf * 8 + g][ks * 8 + tg];
                bb[nf][1] = Ks[wd + nf * 8 + g][ks * 8 + tg + 4];
            }
            #pragma unroll
            for (int mf = 0; mf < 2; mf++)
                #pragma unroll
                for (int nf = 0; nf < 2; nf++)
                    mma_tf32(acc[mf][nf], a[mf], bb[nf]);
        }
    }

    float* cp = g_ctxp + ((size_t)ch * B * NHEADS + bh) * DH * DH;
    #pragma unroll
    for (int mf = 0; mf < 2; mf++) {
        int e = we + mf * 16 + g;
        #pragma unroll
        for (int nf = 0; nf < 2; nf++) {
            int d = wd + nf * 8 + tg * 2;
            *(float2*)(cp + (size_t)e * DH + d)       = make_float2(acc[mf][nf][0], acc[mf][nf][1]);
            *(float2*)(cp + (size_t)(e + 8) * DH + d) = make_float2(acc[mf][nf][2], acc[mf][nf][3]);
        }
    }
}

// =====================================================================
// K5: reduce 13 partial context chunks (deterministic fixed order)
// =====================================================================
__global__ __launch_bounds__(256) void ctx_reduce()
{
    int idx = (blockIdx.x * 256 + threadIdx.x) * 4;    // 512 blocks covers 524288
    float4 s = *(const float4*)(g_ctxp + idx);
    #pragma unroll
    for (int ch = 1; ch < NCHUNK; ch++) {
        float4 v = *(const float4*)(g_ctxp + (size_t)ch * (B * NHEADS * DH * DH) + idx);
        s.x += v.x; s.y += v.y; s.z += v.z; s.w += v.w;
    }
    *(float4*)(g_ctxT + idx) = s;
}

// =====================================================================
// K6: fold context into output weights:
//   Wc[b][o][h*64+d] = sum_e Wout[o][h*64+e] * ctxT[b,h][e][d]
// grid (4 o-tiles, 8 heads, 16 batch)
// =====================================================================
__global__ __launch_bounds__(256) void ctx_fold(const float* __restrict__ Wout)
{
    __shared__ float ctx_s[64][68];      // [e][d]
    __shared__ float w_s[64][68];        // [o_local][e]

    int o0 = blockIdx.x * 64;
    int h  = blockIdx.y;
    int b  = blockIdx.z;
    int bh = b * NHEADS + h;
    int tid = threadIdx.x;

    const float* cp = g_ctxT + (size_t)bh * DH * DH;
    #pragma unroll
    for (int r = 0; r < 4; r++) {
        int f = tid + r * 256;
        int row = f >> 4, c4 = (f & 15) * 4;
        *(float4*)&ctx_s[row][c4] = *(const float4*)(cp + (size_t)row * DH + c4);
        *(float4*)&w_s[row][c4]   = *(const float4*)(Wout + (size_t)(o0 + row) * HID + h * DH + c4);
    }
    __syncthreads();

    int og = tid >> 6;          // 0..3 (16-row o group)
    int d  = tid & 63;
    float acc[16];
    #pragma unroll
    for (int i = 0; i < 16; i++) acc[i] = 0.f;
    #pragma unroll 4
    for (int e = 0; e < 64; e++) {
        float c = ctx_s[e][d];
        #pragma unroll
        for (int i = 0; i < 16; i++)
            acc[i] = fmaf(w_s[og * 16 + i][e], c, acc[i]);
    }
    float* wcp = g_wc + ((size_t)b * C) * HID;
    #pragma unroll
    for (int i = 0; i < 16; i++)
        wcp[(size_t)(o0 + og * 16 + i) * HID + h * DH + d] = acc[i];
}

// =====================================================================
// K7: y = LN( Wc_b @ qexp + bias )   (M=256 full per block, N=128, K=512)
// tf32 mma + in-block channel LayerNorm epilogue. Dynamic smem.
// =====================================================================
#define OUT_SMEM 62464

__global__ __launch_bounds__(256) void gemm_out_ln(
    const float* __restrict__ bias, const float* __restrict__ lng,
    const float* __restrict__ lnb, float* __restrict__ y)
{
    extern __shared__ char dyn[];
    uint32_t (*As)[36]  = (uint32_t(*)[36])dyn;              // 256x36x4  = 36864
    uint32_t (*Bs)[136] = (uint32_t(*)[136])(dyn + 36864);   // 32x136x4  = 17408
    float* swsum = (float*)(dyn + 54272);                    // 4x128
    float* swsq  = (float*)(dyn + 56320);                    // 4x128
    float* sbias = (float*)(dyn + 58368);                    // 256
    float* slg   = (float*)(dyn + 59392);                    // 256
    float* slb   = (float*)(dyn + 60416);                    // 256
    float* smean = (float*)(dyn + 61440);                    // 128
    float* srstd = (float*)(dyn + 61952);                    // 128

    int t0 = blockIdx.x * 128;
    int b  = blockIdx.z;
    int tid  = threadIdx.x;
    int lane = tid & 31, wid = tid >> 5;
    int g = lane >> 2, tg = lane & 3;
    int wm = wid & 3;            // m 64-range
    int wn = wid >> 2;           // n 64-range

    sbias[tid] = bias[tid];
    slg[tid]   = lng[tid];
    slb[tid]   = lnb[tid];

    const float* Ap = g_wc + (size_t)b * C * HID;
    const float* Bp = g_qexp + (size_t)b * HID * HW;

    float acc[4][8][4];
    #pragma unroll
    for (int mf = 0; mf < 4; mf++)
        #pragma unroll
        for (int nf = 0; nf < 8; nf++)
            #pragma unroll
            for (int i = 0; i < 4; i++) acc[mf][nf][i] = 0.f;

    for (int k0 = 0; k0 < HID; k0 += 32) {
        __syncthreads();
        #pragma unroll
        for (int r = 0; r < 8; r++) {
            int idx = tid + r * 256;         // 2048 float4 slots
            int row = idx >> 3;
            int kc  = (idx & 7) * 4;
            float4 v = *(const float4*)(Ap + (size_t)row * HID + k0 + kc);
            As[row][kc + 0] = f2tf32(v.x);
            As[row][kc + 1] = f2tf32(v.y);
            As[row][kc + 2] = f2tf32(v.z);
            As[row][kc + 3] = f2tf32(v.w);
        }
        #pragma unroll
        for (int r = 0; r < 4; r++) {
            int idx = tid + r * 256;
            int row = idx >> 5;
            int nc  = (idx & 31) * 4;
            float4 v = *(const float4*)(Bp + (size_t)(k0 + row) * HW + t0 + nc);
            Bs[row][nc + 0] = f2tf32(v.x);
            Bs[row][nc + 1] = f2tf32(v.y);
            Bs[row][nc + 2] = f2tf32(v.z);
            Bs[row][nc + 3] = f2tf32(v.w);
        }
        __syncthreads();
        #pragma unroll
        for (int ks = 0; ks < 4; ks++) {
            uint32_t a[4][4], bb[8][2];
            #pragma unroll
            for (int mf = 0; mf < 4; mf++) {
                int row = wm * 64 + mf * 16 + g;
                a[mf][0] = As[row    ][ks * 8 + tg];
                a[mf][1] = As[row + 8][ks * 8 + tg];
                a[mf][2] = As[row    ][ks * 8 + tg + 4];
                a[mf][3] = As[row + 8][ks * 8 + tg + 4];
            }
            #pragma unroll
            for (int nf = 0; nf < 8; nf++) {
                bb[nf][0] = Bs[ks * 8 + tg    ][wn * 64 + nf * 8 + g];
                bb[nf][1] = Bs[ks * 8 + tg + 4][wn * 64 + nf * 8 + g];
            }
            #pragma unroll
            for (int mf = 0; mf < 4; mf++)
                #pragma unroll
                for (int nf = 0; nf < 8; nf++)
                    mma_tf32(acc[mf][nf], a[mf], bb[nf]);
        }
    }

    // ---- LayerNorm over o=256 per token ----
    // per-thread partials for its 16 t-columns (nf x 2)
    float psum[16], psq[16];
    #pragma unroll
    for (int j = 0; j < 16; j++) { psum[j] = 0.f; psq[j] = 0.f; }
    #pragma unroll
    for (int mf = 0; mf < 4; mf++) {
        int o0r = wm * 64 + mf * 16 + g;
        float b0 = sbias[o0r], b1 = sbias[o0r + 8];
        #pragma unroll
        for (int nf = 0; nf < 8; nf++) {
            #pragma unroll
            for (int bc = 0; bc < 2; bc++) {
                float v0 = acc[mf][nf][bc]     + b0;
                float v1 = acc[mf][nf][2 + bc] + b1;
                psum[nf * 2 + bc] += v0 + v1;
                psq[nf * 2 + bc]  += v0 * v0 + v1 * v1;
            }
        }
    }
    #pragma unroll
    for (int o = 4; o <= 16; o <<= 1) {
        #pragma unroll
        for (int j = 0; j < 16; j++) {
            psum[j] += __shfl_xor_sync(0xffffffffu, psum[j], o);
            psq[j]  += __shfl_xor_sync(0xffffffffu, psq[j], o);
        }
    }
    __syncthreads();       // protect smem reuse ordering
    if (g == 0) {
        #pragma unroll
        for (int nf = 0; nf < 8; nf++)
            #pragma unroll
            for (int bc = 0; bc < 2; bc++) {
                int tl = wn * 64 + nf * 8 + tg * 2 + bc;
                swsum[wm * 128 + tl] = psum[nf * 2 + bc];
                swsq[wm * 128 + tl]  = psq[nf * 2 + bc];
            }
    }
    __syncthreads();
    if (tid < 128) {
        float s  = swsum[tid] + swsum[128 + tid] + swsum[256 + tid] + swsum[384 + tid];
        float sq = swsq[tid]  + swsq[128 + tid]  + swsq[256 + tid]  + swsq[384 + tid];
        float mean = s * (1.f / 256.f);
        float var  = sq * (1.f / 256.f) - mean * mean;
        smean[tid] = mean;
        srstd[tid] = rsqrtf(var + 1e-5f);
    }
    __syncthreads();

    float* outp = y + (size_t)b * C * HW;
    #pragma unroll
    for (int mf = 0; mf < 4; mf++) {
        int o0r = wm * 64 + mf * 16 + g;
        float b0 = sbias[o0r],   g0 = slg[o0r],   be0 = slb[o0r];
        float b1 = sbias[o0r+8], g1 = slg[o0r+8], be1 = slb[o0r+8];
        #pragma unroll
        for (int nf = 0; nf < 8; nf++) {
            int tl = wn * 64 + nf * 8 + tg * 2;
            float m0 = smean[tl], m1 = smean[tl + 1];
            float r0 = srstd[tl], r1 = srstd[tl + 1];
            float2 v0, v1;
            v0.x = (acc[mf][nf][0] + b0 - m0) * r0 * g0 + be0;
            v0.y = (acc[mf][nf][1] + b0 - m1) * r1 * g0 + be0;
            v1.x = (acc[mf][nf][2] + b1 - m0) * r0 * g1 + be1;
            v1.y = (acc[mf][nf][3] + b1 - m1) * r1 * g1 + be1;
            *(float2*)(outp + (size_t)o0r * HW + t0 + tl)       = v0;
            *(float2*)(outp + (size_t)(o0r + 8) * HW + t0 + tl) = v1;
        }
    }
}

// =====================================================================
extern "C" void kernel_launch(void* const* d_in, const int* in_sizes, int n_in,
                              void* d_out, int out_size)
{
    const float* x    = (const float*)d_in[0];
    const float* mem  = (const float*)d_in[1];
    const float* Wqkv = (const float*)d_in[2];
    const float* Wout = (const float*)d_in[3];
    const float* bout = (const float*)d_in[4];
    const float* lng  = (const float*)d_in[5];
    const float* lnb  = (const float*)d_in[6];
    float* y = (float*)d_out;

    cudaFuncSetAttribute(gemm_out_ln, cudaFuncAttributeMaxDynamicSharedMemorySize, OUT_SMEM);

    gemm_qkv<<<dim3(33, 12, B), 256>>>(x, mem, Wqkv);
    k_stats<<<B * HID, 256>>>();
    q_softmax<<<dim3(HW / 128, NHEADS, B), 256>>>();
    k_context_p<<<dim3(NCHUNK, NHEADS, B), 256>>>();
    ctx_reduce<<<512, 256>>>();
    ctx_fold<<<dim3(4, NHEADS, B), 256>>>(Wout);
    gemm_out_ln<<<dim3(HW / 128, 1, B), 256, OUT_SMEM>>>(bout, lng, lnb, y);
}

// round 7
// speedup vs baseline: 3.2685x; 1.1278x over previous
#include <cuda_runtime.h>
#include <math.h>
#include <stdint.h>

#define B      16
#define C      256
#define HW     4096
#define MEM    64
#define NTOK   4160
#define H3     1536
#define HID    512
#define NHEADS 8
#define DH     64
#define NCHUNK 13
#define CHTOK  320     // NTOK / NCHUNK
#define NTILES 33      // gemm_qkv n-tiles

// -------- scratch (device globals, fully overwritten every launch) --------
__device__ float g_qkv[(size_t)B * H3 * NTOK];     // k rows 512..1023 hold exp(k); v rows 1024..1535; q region unused
__device__ float g_ksump[NTILES * B * HID];        // per-n-tile partial sums of exp(k)
__device__ float g_kinv[B * HID];                  // 1 / total sum
__device__ float g_qexp[(size_t)B * HID * HW];     // softmaxed+scaled q, [b][h*64+d][t]
__device__ float g_ctxp[(size_t)NCHUNK * B * NHEADS * DH * DH];  // partial ctxT [ch][bh][e][d]
__device__ float g_ctxT[B * NHEADS * DH * DH];     // ctxT [bh][e][d], inv applied
__device__ float g_wc[(size_t)B * C * HID];        // folded weights [b][o][h*64+d]

// ---------------- tf32 mma helpers ----------------
__device__ __forceinline__ uint32_t f2tf32(float f) {
    uint32_t r;
    asm("cvt.rna.tf32.f32 %0, %1;" : "=r"(r) : "f"(f));
    return r;
}

__device__ __forceinline__ void mma_tf32(float* d, const uint32_t* a, const uint32_t* b) {
    asm volatile(
        "mma.sync.aligned.m16n8k8.row.col.f32.tf32.tf32.f32 "
        "{%0,%1,%2,%3}, {%4,%5,%6,%7}, {%8,%9}, {%0,%1,%2,%3};\n"
        : "+f"(d[0]), "+f"(d[1]), "+f"(d[2]), "+f"(d[3])
        : "r"(a[0]), "r"(a[1]), "r"(a[2]), "r"(a[3]), "r"(b[0]), "r"(b[1]));
}

// =====================================================================
// K1: qkv = W_qkv @ x_ext  (tf32 MMA) with fused epilogues:
//  - q rows (m0<512): softmax over d in-register -> write g_qexp directly
//  - k rows (512..1023): store exp(k); per-row partial sums -> g_ksump
//  - v rows: plain store
// =====================================================================
__global__ __launch_bounds__(256) void gemm_qkv(
    const float* __restrict__ x, const float* __restrict__ mem,
    const float* __restrict__ W)
{
    __shared__ uint32_t As[128][36];
    __shared__ uint32_t Bs[32][136];
    __shared__ float psum[4][128];      // k partial sums [warp_n group][row]

    int b  = blockIdx.z;
    int m0 = blockIdx.y * 128;
    int n0 = blockIdx.x * 128;
    int tid  = threadIdx.x;
    int lane = tid & 31, wid = tid >> 5;
    int warp_m = (wid & 1) * 64;
    int warp_n = (wid >> 1) * 32;
    int g = lane >> 2, tg = lane & 3;

    const float* src;
    int stride, col0, ncols;
    if (n0 < HW) { src = x + (size_t)b * C * HW; stride = HW;  col0 = n0; ncols = 128; }
    else {
        if (m0 < HID) return;            // q not needed at memory tokens
        src = mem; stride = MEM; col0 = 0; ncols = MEM;
    }

    float acc[4][4][4];
    #pragma unroll
    for (int mf = 0; mf < 4; mf++)
        #pragma unroll
        for (int nf = 0; nf < 4; nf++)
            #pragma unroll
            for (int i = 0; i < 4; i++) acc[mf][nf][i] = 0.f;

    for (int k0 = 0; k0 < C; k0 += 32) {
        __syncthreads();
        #pragma unroll
        for (int r = 0; r < 4; r++) {
            int idx = tid + r * 256;
            int row = idx >> 3;
            int kc  = (idx & 7) * 4;
            float4 v = *(const float4*)(W + (size_t)(m0 + row) * C + k0 + kc);
            As[row][kc + 0] = f2tf32(v.x);
            As[row][kc + 1] = f2tf32(v.y);
            As[row][kc + 2] = f2tf32(v.z);
            As[row][kc + 3] = f2tf32(v.w);
        }
        #pragma unroll
        for (int r = 0; r < 4; r++) {
            int idx = tid + r * 256;
            int row = idx >> 5;
            int nc  = (idx & 31) * 4;
            float4 v;
            if (nc + 3 < ncols)
                v = *(const float4*)(src + (size_t)(k0 + row) * stride + col0 + nc);
            else
                v = make_float4(0.f, 0.f, 0.f, 0.f);
            Bs[row][nc + 0] = f2tf32(v.x);
            Bs[row][nc + 1] = f2tf32(v.y);
            Bs[row][nc + 2] = f2tf32(v.z);
            Bs[row][nc + 3] = f2tf32(v.w);
        }
        __syncthreads();
        #pragma unroll
        for (int ks = 0; ks < 4; ks++) {
            uint32_t a[4][4], bb[4][2];
            #pragma unroll
            for (int mf = 0; mf < 4; mf++) {
                int row = warp_m + mf * 16 + g;
                a[mf][0] = As[row    ][ks * 8 + tg];
                a[mf][1] = As[row + 8][ks * 8 + tg];
                a[mf][2] = As[row    ][ks * 8 + tg + 4];
                a[mf][3] = As[row + 8][ks * 8 + tg + 4];
            }
            #pragma unroll
            for (int nf = 0; nf < 4; nf++) {
                bb[nf][0] = Bs[ks * 8 + tg    ][warp_n + nf * 8 + g];
                bb[nf][1] = Bs[ks * 8 + tg + 4][warp_n + nf * 8 + g];
            }
            #pragma unroll
            for (int mf = 0; mf < 4; mf++)
                #pragma unroll
                for (int nf = 0; nf < 4; nf++)
                    mma_tf32(acc[mf][nf], a[mf], bb[nf]);
        }
    }

    if (m0 < HID) {
        // ---- q: softmax over d (warp's 64 m-rows = one full head) ----
        #pragma unroll
        for (int nf = 0; nf < 4; nf++) {
            #pragma unroll
            for (int bc = 0; bc < 2; bc++) {
                float s = 0.f;
                #pragma unroll
                for (int mf = 0; mf < 4; mf++) {
                    float e0 = __expf(acc[mf][nf][bc]);
                    float e1 = __expf(acc[mf][nf][2 + bc]);
                    acc[mf][nf][bc]     = e0;
                    acc[mf][nf][2 + bc] = e1;
                    s += e0 + e1;
                }
                s += __shfl_xor_sync(0xffffffffu, s, 4);
                s += __shfl_xor_sync(0xffffffffu, s, 8);
                s += __shfl_xor_sync(0xffffffffu, s, 16);
                float sc = 0.125f / s;            // SCALE folded
                #pragma unroll
                for (int mf = 0; mf < 4; mf++) {
                    acc[mf][nf][bc]     *= sc;
                    acc[mf][nf][2 + bc] *= sc;
                }
            }
        }
        float* op = g_qexp + (size_t)b * HID * HW;
        #pragma unroll
        for (int mf = 0; mf < 4; mf++) {
            int m = m0 + warp_m + mf * 16 + g;
            #pragma unroll
            for (int nf = 0; nf < 4; nf++) {
                int t = n0 + warp_n + nf * 8 + tg * 2;
                *(float2*)(op + (size_t)m * HW + t) =
                    make_float2(acc[mf][nf][0], acc[mf][nf][1]);
                *(float2*)(op + (size_t)(m + 8) * HW + t) =
                    make_float2(acc[mf][nf][2], acc[mf][nf][3]);
            }
        }
        return;
    }

    bool is_k = (m0 < 2 * HID);
    if (is_k) {
        // exponentiate in place, then per-row partial sums over valid columns
        #pragma unroll
        for (int mf = 0; mf < 4; mf++)
            #pragma unroll
            for (int nf = 0; nf < 4; nf++)
                #pragma unroll
                for (int i = 0; i < 4; i++)
                    acc[mf][nf][i] = __expf(acc[mf][nf][i]);

        #pragma unroll
        for (int mf = 0; mf < 4; mf++) {
            #pragma unroll
            for (int half = 0; half < 2; half++) {
                float s = 0.f;
                #pragma unroll
                for (int nf = 0; nf < 4; nf++) {
                    #pragma unroll
                    for (int bc = 0; bc < 2; bc++) {
                        int n = warp_n + nf * 8 + tg * 2 + bc;
                        float v = acc[mf][nf][half * 2 + bc];
                        s += (n0 + n < NTOK) ? v : 0.f;
                    }
                }
                s += __shfl_xor_sync(0xffffffffu, s, 1);
                s += __shfl_xor_sync(0xffffffffu, s, 2);
                if (tg == 0)
                    psum[wid >> 1][warp_m + mf * 16 + g + half * 8] = s;
            }
        }
        __syncthreads();
        if (tid < 128) {
            float s = psum[0][tid] + psum[1][tid] + psum[2][tid] + psum[3][tid];
            g_ksump[(size_t)blockIdx.x * (B * HID) + b * HID + (m0 - HID) + tid] = s;
        }
    }

    // ---- store k (ek) / v rows ----
    float* outp = g_qkv + (size_t)b * H3 * NTOK;
    #pragma unroll
    for (int mf = 0; mf < 4; mf++) {
        #pragma unroll
        for (int nf = 0; nf < 4; nf++) {
            int n = n0 + warp_n + nf * 8 + tg * 2;
            if (n < NTOK) {
                int m = m0 + warp_m + mf * 16 + g;
                *(float2*)(outp + (size_t)m * NTOK + n) =
                    make_float2(acc[mf][nf][0], acc[mf][nf][1]);
                *(float2*)(outp + (size_t)(m + 8) * NTOK + n) =
                    make_float2(acc[mf][nf][2], acc[mf][nf][3]);
            }
        }
    }
}

// =====================================================================
// K2: reduce per-tile k sums -> g_kinv = 1/total   (8192 rows, 33 tiles)
// =====================================================================
__global__ __launch_bounds__(256) void k_stats_reduce()
{
    int row = blockIdx.x * 256 + threadIdx.x;     // 0..8191
    float s = 0.f;
    #pragma unroll
    for (int nt = 0; nt < NTILES; nt++)
        s += g_ksump[(size_t)nt * (B * HID) + row];
    g_kinv[row] = 1.f / s;
}

// =====================================================================
// K3: partial ctxT[e][d] = sum_n v[e,n] * ek[d,n] over a 320-token chunk
// (normalization 1/sum applied later in ctx_reduce)
// =====================================================================
__global__ __launch_bounds__(256) void k_context_p()
{
    __shared__ uint32_t Ks[64][68];       // ek[d][nt]  (B operand, n=d)
    __shared__ uint32_t Vs[64][68];       // v[e][nt]   (A operand, m=e)

    int ch = blockIdx.x;
    int h  = blockIdx.y;
    int b  = blockIdx.z;
    int bh = b * NHEADS + h;
    const float* kp = g_qkv + ((size_t)b * H3 + HID     + h * DH) * NTOK;
    const float* vp = g_qkv + ((size_t)b * H3 + 2 * HID + h * DH) * NTOK;

    int tid = threadIdx.x;
    int lane = tid & 31, wid = tid >> 5;
    int g = lane >> 2, tg = lane & 3;
    int we = (wid & 1) * 32;
    int wd = (wid >> 1) * 16;

    float acc[2][2][4];
    #pragma unroll
    for (int mf = 0; mf < 2; mf++)
        #pragma unroll
        for (int nf = 0; nf < 2; nf++)
            #pragma unroll
            for (int i = 0; i < 4; i++) acc[mf][nf][i] = 0.f;

    for (int tile = 0; tile < CHTOK / 64; tile++) {
        int n0 = ch * CHTOK + tile * 64;
        __syncthreads();
        #pragma unroll
        for (int r = 0; r < 4; r++) {
            int f = tid + r * 256;
            int row = f >> 4, c4 = (f & 15) * 4;
            float4 kv = *(const float4*)(kp + (size_t)row * NTOK + n0 + c4);
            Ks[row][c4 + 0] = f2tf32(kv.x);
            Ks[row][c4 + 1] = f2tf32(kv.y);
            Ks[row][c4 + 2] = f2tf32(kv.z);
            Ks[row][c4 + 3] = f2tf32(kv.w);
            float4 vv = *(const float4*)(vp + (size_t)row * NTOK + n0 + c4);
            Vs[row][c4 + 0] = f2tf32(vv.x);
            Vs[row][c4 + 1] = f2tf32(vv.y);
            Vs[row][c4 + 2] = f2tf32(vv.z);
            Vs[row][c4 + 3] = f2tf32(vv.w);
        }
        __syncthreads();
        #pragma unroll
        for (int ks = 0; ks < 8; ks++) {
            uint32_t a[2][4], bb[2][2];
            #pragma unroll
            for (int mf = 0; mf < 2; mf++) {
                int row = we + mf * 16 + g;
                a[mf][0] = Vs[row    ][ks * 8 + tg];
                a[mf][1] = Vs[row + 8][ks * 8 + tg];
                a[mf][2] = Vs[row    ][ks * 8 + tg + 4];
                a[mf][3] = Vs[row + 8][ks * 8 + tg + 4];
            }
            #pragma unroll
            for (int nf = 0; nf < 2; nf++) {
                bb[nf][0] = Ks[wd + nf * 8 + g][ks * 8 + tg];
                bb[nf][1] = Ks[wd + nf * 8 + g][ks * 8 + tg + 4];
            }
            #pragma unroll
            for (int mf = 0; mf < 2; mf++)
                #pragma unroll
                for (int nf = 0; nf < 2; nf++)
                    mma_tf32(acc[mf][nf], a[mf], bb[nf]);
        }
    }

    float* cp = g_ctxp + ((size_t)ch * B * NHEADS + bh) * DH * DH;
    #pragma unroll
    for (int mf = 0; mf < 2; mf++) {
        int e = we + mf * 16 + g;
        #pragma unroll
        for (int nf = 0; nf < 2; nf++) {
            int d = wd + nf * 8 + tg * 2;
            *(float2*)(cp + (size_t)e * DH + d)       = make_float2(acc[mf][nf][0], acc[mf][nf][1]);
            *(float2*)(cp + (size_t)(e + 8) * DH + d) = make_float2(acc[mf][nf][2], acc[mf][nf][3]);
        }
    }
}

// =====================================================================
// K4: reduce 13 partial context chunks + apply 1/sum column scale
// =====================================================================
__global__ __launch_bounds__(256) void ctx_reduce()
{
    int idx = (blockIdx.x * 256 + threadIdx.x) * 4;    // 512 blocks covers 524288
    float4 s = *(const float4*)(g_ctxp + idx);
    #pragma unroll
    for (int ch = 1; ch < NCHUNK; ch++) {
        float4 v = *(const float4*)(g_ctxp + (size_t)ch * (B * NHEADS * DH * DH) + idx);
        s.x += v.x; s.y += v.y; s.z += v.z; s.w += v.w;
    }
    int bh = idx >> 12;          // 4096 elements per bh
    int d  = idx & 63;
    float4 inv = *(const float4*)(g_kinv + bh * 64 + d);
    s.x *= inv.x; s.y *= inv.y; s.z *= inv.z; s.w *= inv.w;
    *(float4*)(g_ctxT + idx) = s;
}

// =====================================================================
// K5: fold context into output weights:
//   Wc[b][o][h*64+d] = sum_e Wout[o][h*64+e] * ctxT[b,h][e][d]
// =====================================================================
__global__ __launch_bounds__(256) void ctx_fold(const float* __restrict__ Wout)
{
    __shared__ float ctx_s[64][68];      // [e][d]
    __shared__ float w_s[64][68];        // [o_local][e]

    int o0 = blockIdx.x * 64;
    int h  = blockIdx.y;
    int b  = blockIdx.z;
    int bh = b * NHEADS + h;
    int tid = threadIdx.x;

    const float* cp = g_ctxT + (size_t)bh * DH * DH;
    #pragma unroll
    for (int r = 0; r < 4; r++) {
        int f = tid + r * 256;
        int row = f >> 4, c4 = (f & 15) * 4;
        *(float4*)&ctx_s[row][c4] = *(const float4*)(cp + (size_t)row * DH + c4);
        *(float4*)&w_s[row][c4]   = *(const float4*)(Wout + (size_t)(o0 + row) * HID + h * DH + c4);
    }
    __syncthreads();

    int og = tid >> 6;
    int d  = tid & 63;
    float acc[16];
    #pragma unroll
    for (int i = 0; i < 16; i++) acc[i] = 0.f;
    #pragma unroll 4
    for (int e = 0; e < 64; e++) {
        float c = ctx_s[e][d];
        #pragma unroll
        for (int i = 0; i < 16; i++)
            acc[i] = fmaf(w_s[og * 16 + i][e], c, acc[i]);
    }
    float* wcp = g_wc + ((size_t)b * C) * HID;
    #pragma unroll
    for (int i = 0; i < 16; i++)
        wcp[(size_t)(o0 + og * 16 + i) * HID + h * DH + d] = acc[i];
}

// =====================================================================
// K6: y = LN( Wc_b @ qexp + bias )   (M=256 per block, N=128, K=512)
// =====================================================================
#define OUT_SMEM 62464

__global__ __launch_bounds__(256) void gemm_out_ln(
    const float* __restrict__ bias, const float* __restrict__ lng,
    const float* __restrict__ lnb, float* __restrict__ y)
{
    extern __shared__ char dyn[];
    uint32_t (*As)[36]  = (uint32_t(*)[36])dyn;              // 256x36x4  = 36864
    uint32_t (*Bs)[136] = (uint32_t(*)[136])(dyn + 36864);   // 32x136x4  = 17408
    float* swsum = (float*)(dyn + 54272);
    float* swsq  = (float*)(dyn + 56320);
    float* sbias = (float*)(dyn + 58368);
    float* slg   = (float*)(dyn + 59392);
    float* slb   = (float*)(dyn + 60416);
    float* smean = (float*)(dyn + 61440);
    float* srstd = (float*)(dyn + 61952);

    int t0 = blockIdx.x * 128;
    int b  = blockIdx.z;
    int tid  = threadIdx.x;
    int lane = tid & 31, wid = tid >> 5;
    int g = lane >> 2, tg = lane & 3;
    int wm = wid & 3;
    int wn = wid >> 2;

    sbias[tid] = bias[tid];
    slg[tid]   = lng[tid];
    slb[tid]   = lnb[tid];

    const float* Ap = g_wc + (size_t)b * C * HID;
    const float* Bp = g_qexp + (size_t)b * HID * HW;

    float acc[4][8][4];
    #pragma unroll
    for (int mf = 0; mf < 4; mf++)
        #pragma unroll
        for (int nf = 0; nf < 8; nf++)
            #pragma unroll
            for (int i = 0; i < 4; i++) acc[mf][nf][i] = 0.f;

    for (int k0 = 0; k0 < HID; k0 += 32) {
        __syncthreads();
        #pragma unroll
        for (int r = 0; r < 8; r++) {
            int idx = tid + r * 256;
            int row = idx >> 3;
            int kc  = (idx & 7) * 4;
            float4 v = *(const float4*)(Ap + (size_t)row * HID + k0 + kc);
            As[row][kc + 0] = f2tf32(v.x);
            As[row][kc + 1] = f2tf32(v.y);
            As[row][kc + 2] = f2tf32(v.z);
            As[row][kc + 3] = f2tf32(v.w);
        }
        #pragma unroll
        for (int r = 0; r < 4; r++) {
            int idx = tid + r * 256;
            int row = idx >> 5;
            int nc  = (idx & 31) * 4;
            float4 v = *(const float4*)(Bp + (size_t)(k0 + row) * HW + t0 + nc);
            Bs[row][nc + 0] = f2tf32(v.x);
            Bs[row][nc + 1] = f2tf32(v.y);
            Bs[row][nc + 2] = f2tf32(v.z);
            Bs[row][nc + 3] = f2tf32(v.w);
        }
        __syncthreads();
        #pragma unroll
        for (int ks = 0; ks < 4; ks++) {
            uint32_t a[4][4], bb[8][2];
            #pragma unroll
            for (int mf = 0; mf < 4; mf++) {
                int row = wm * 64 + mf * 16 + g;
                a[mf][0] = As[row    ][ks * 8 + tg];
                a[mf][1] = As[row + 8][ks * 8 + tg];
                a[mf][2] = As[row    ][ks * 8 + tg + 4];
                a[mf][3] = As[row + 8][ks * 8 + tg + 4];
            }
            #pragma unroll
            for (int nf = 0; nf < 8; nf++) {
                bb[nf][0] = Bs[ks * 8 + tg    ][wn * 64 + nf * 8 + g];
                bb[nf][1] = Bs[ks * 8 + tg + 4][wn * 64 + nf * 8 + g];
            }
            #pragma unroll
            for (int mf = 0; mf < 4; mf++)
                #pragma unroll
                for (int nf = 0; nf < 8; nf++)
                    mma_tf32(acc[mf][nf], a[mf], bb[nf]);
        }
    }

    // ---- LayerNorm over o=256 per token ----
    float psum[16], psq[16];
    #pragma unroll
    for (int j = 0; j < 16; j++) { psum[j] = 0.f; psq[j] = 0.f; }
    #pragma unroll
    for (int mf = 0; mf < 4; mf++) {
        int o0r = wm * 64 + mf * 16 + g;
        float b0 = sbias[o0r], b1 = sbias[o0r + 8];
        #pragma unroll
        for (int nf = 0; nf < 8; nf++) {
            #pragma unroll
            for (int bc = 0; bc < 2; bc++) {
                float v0 = acc[mf][nf][bc]     + b0;
                float v1 = acc[mf][nf][2 + bc] + b1;
                psum[nf * 2 + bc] += v0 + v1;
                psq[nf * 2 + bc]  += v0 * v0 + v1 * v1;
            }
        }
    }
    #pragma unroll
    for (int o = 4; o <= 16; o <<= 1) {
        #pragma unroll
        for (int j = 0; j < 16; j++) {
            psum[j] += __shfl_xor_sync(0xffffffffu, psum[j], o);
            psq[j]  += __shfl_xor_sync(0xffffffffu, psq[j], o);
        }
    }
    __syncthreads();
    if (g == 0) {
        #pragma unroll
        for (int nf = 0; nf < 8; nf++)
            #pragma unroll
            for (int bc = 0; bc < 2; bc++) {
                int tl = wn * 64 + nf * 8 + tg * 2 + bc;
                swsum[wm * 128 + tl] = psum[nf * 2 + bc];
                swsq[wm * 128 + tl]  = psq[nf * 2 + bc];
            }
    }
    __syncthreads();
    if (tid < 128) {
        float s  = swsum[tid] + swsum[128 + tid] + swsum[256 + tid] + swsum[384 + tid];
        float sq = swsq[tid]  + swsq[128 + tid]  + swsq[256 + tid]  + swsq[384 + tid];
        float mean = s * (1.f / 256.f);
        float var  = sq * (1.f / 256.f) - mean * mean;
        smean[tid] = mean;
        srstd[tid] = rsqrtf(var + 1e-5f);
    }
    __syncthreads();

    float* outp = y + (size_t)b * C * HW;
    #pragma unroll
    for (int mf = 0; mf < 4; mf++) {
        int o0r = wm * 64 + mf * 16 + g;
        float b0 = sbias[o0r],   g0 = slg[o0r],   be0 = slb[o0r];
        float b1 = sbias[o0r+8], g1 = slg[o0r+8], be1 = slb[o0r+8];
        #pragma unroll
        for (int nf = 0; nf < 8; nf++) {
            int tl = wn * 64 + nf * 8 + tg * 2;
            float m0 = smean[tl], m1 = smean[tl + 1];
            float r0 = srstd[tl], r1 = srstd[tl + 1];
            float2 v0, v1;
            v0.x = (acc[mf][nf][0] + b0 - m0) * r0 * g0 + be0;
            v0.y = (acc[mf][nf][1] + b0 - m1) * r1 * g0 + be0;
            v1.x = (acc[mf][nf][2] + b1 - m0) * r0 * g1 + be1;
            v1.y = (acc[mf][nf][3] + b1 - m1) * r1 * g1 + be1;
            *(float2*)(outp + (size_t)o0r * HW + t0 + tl)       = v0;
            *(float2*)(outp + (size_t)(o0r + 8) * HW + t0 + tl) = v1;
        }
    }
}

// =====================================================================
extern "C" void kernel_launch(void* const* d_in, const int* in_sizes, int n_in,
                              void* d_out, int out_size)
{
    const float* x    = (const float*)d_in[0];
    const float* mem  = (const float*)d_in[1];
    const float* Wqkv = (const float*)d_in[2];
    const float* Wout = (const float*)d_in[3];
    const float* bout = (const float*)d_in[4];
    const float* lng  = (const float*)d_in[5];
    const float* lnb  = (const float*)d_in[6];
    float* y = (float*)d_out;

    cudaFuncSetAttribute(gemm_out_ln, cudaFuncAttributeMaxDynamicSharedMemorySize, OUT_SMEM);

    gemm_qkv<<<dim3(NTILES, 12, B), 256>>>(x, mem, Wqkv);
    k_stats_reduce<<<32, 256>>>();
    k_context_p<<<dim3(NCHUNK, NHEADS, B), 256>>>();
    ctx_reduce<<<512, 256>>>();
    ctx_fold<<<dim3(4, NHEADS, B), 256>>>(Wout);
    gemm_out_ln<<<dim3(HW / 128, 1, B), 256, OUT_SMEM>>>(bout, lng, lnb, y);
}